// round 2
// baseline (speedup 1.0000x reference)
#include <cuda_runtime.h>

#define BB 16
#define SS 4096
#define HH 1024

// scratch: dec_fea [B,H]
__device__ float g_dec[BB * HH];

__device__ __forceinline__ float tanh_fast(float x) {
    float y;
    asm("tanh.approx.f32 %0, %1;" : "=f"(y) : "f"(x));
    return y;
}

__device__ __forceinline__ float warp_sum(float v) {
#pragma unroll
    for (int o = 16; o > 0; o >>= 1) v += __shfl_xor_sync(0xffffffffu, v, o);
    return v;
}

__device__ __forceinline__ float warp_max(float v) {
#pragma unroll
    for (int o = 16; o > 0; o >>= 1) v = fmaxf(v, __shfl_xor_sync(0xffffffffu, v, o));
    return v;
}

// ---------------------------------------------------------------------------
// K1: dec[b][h] = sum_k s_t_hat[b][k] * W_dec[h][k] + b_dec[h]
// warp-per-h, all 16 batches per warp. grid = H/8 = 128 blocks, 256 threads.
// ---------------------------------------------------------------------------
__global__ void k_decproj(const float* __restrict__ s_t,
                          const float* __restrict__ W,
                          const float* __restrict__ bias) {
    int warp = threadIdx.x >> 5, lane = threadIdx.x & 31;
    int h = blockIdx.x * 8 + warp;

    float acc[BB];
#pragma unroll
    for (int b = 0; b < BB; b++) acc[b] = 0.f;

    const float4* Wrow = reinterpret_cast<const float4*>(W + (size_t)h * HH);
#pragma unroll
    for (int it = 0; it < 8; it++) {
        int k4 = it * 32 + lane;
        float4 w = __ldg(Wrow + k4);
#pragma unroll
        for (int b = 0; b < BB; b++) {
            float4 s4 = __ldg(reinterpret_cast<const float4*>(s_t + b * HH) + k4);
            acc[b] += w.x * s4.x + w.y * s4.y + w.z * s4.z + w.w * s4.w;
        }
    }
#pragma unroll
    for (int b = 0; b < BB; b++) {
        float r = warp_sum(acc[b]);
        if (lane == 0) g_dec[b * HH + h] = r + bias[h];
    }
}

// ---------------------------------------------------------------------------
// K2: scores[b][s] = sum_h tanh(ef[b,s,h] + dec[b,h] + cov[b,s]*Wc[h]) * v[h]
// Each warp handles 4 rows; smem operand float4 loaded ONCE per iteration and
// reused for all 4 rows; 4 independent global loads per iteration (MLP x4).
// Block = 256 thr (8 warps) -> 32 rows/block. grid = B*S/32 = 2048.
// ---------------------------------------------------------------------------
#define ROWS_PER_WARP 4
__global__ void k_scores(const float* __restrict__ ef,
                         const float* __restrict__ cov,
                         const float* __restrict__ Wc,
                         const float* __restrict__ v,
                         float* __restrict__ scores) {
    __shared__ float dec_sm[HH], wc_sm[HH], v_sm[HH];
    const int rows_per_block = 8 * ROWS_PER_WARP;  // 32
    int b  = blockIdx.x / (SS / rows_per_block);
    int s0 = (blockIdx.x % (SS / rows_per_block)) * rows_per_block;

    for (int i = threadIdx.x; i < HH / 4; i += blockDim.x) {
        reinterpret_cast<float4*>(dec_sm)[i] = reinterpret_cast<const float4*>(g_dec + b * HH)[i];
        reinterpret_cast<float4*>(wc_sm)[i]  = reinterpret_cast<const float4*>(Wc)[i];
        reinterpret_cast<float4*>(v_sm)[i]   = reinterpret_cast<const float4*>(v)[i];
    }
    __syncthreads();

    int warp = threadIdx.x >> 5, lane = threadIdx.x & 31;
    int s = s0 + warp * ROWS_PER_WARP;

    float c[ROWS_PER_WARP];
    const float4* efr[ROWS_PER_WARP];
#pragma unroll
    for (int r = 0; r < ROWS_PER_WARP; r++) {
        c[r] = __ldg(cov + b * SS + s + r);
        efr[r] = reinterpret_cast<const float4*>(ef + ((size_t)(b * SS + s + r)) * HH);
    }

    float acc[ROWS_PER_WARP];
#pragma unroll
    for (int r = 0; r < ROWS_PER_WARP; r++) acc[r] = 0.f;

#pragma unroll
    for (int it = 0; it < 8; it++) {
        int k4 = it * 32 + lane;
        float4 d  = reinterpret_cast<const float4*>(dec_sm)[k4];
        float4 w  = reinterpret_cast<const float4*>(wc_sm)[k4];
        float4 vv = reinterpret_cast<const float4*>(v_sm)[k4];
        float4 f[ROWS_PER_WARP];
#pragma unroll
        for (int r = 0; r < ROWS_PER_WARP; r++) f[r] = __ldg(efr[r] + k4);
#pragma unroll
        for (int r = 0; r < ROWS_PER_WARP; r++) {
            acc[r] += tanh_fast(f[r].x + d.x + c[r] * w.x) * vv.x;
            acc[r] += tanh_fast(f[r].y + d.y + c[r] * w.y) * vv.y;
            acc[r] += tanh_fast(f[r].z + d.z + c[r] * w.z) * vv.z;
            acc[r] += tanh_fast(f[r].w + d.w + c[r] * w.w) * vv.w;
        }
    }
#pragma unroll
    for (int r = 0; r < ROWS_PER_WARP; r++) {
        float t = warp_sum(acc[r]);
        if (lane == 0) scores[b * SS + s + r] = t;
    }
}

// ---------------------------------------------------------------------------
// K3: masked softmax + renorm per batch; writes attn into BOTH attn regions,
// zeroes the c_t region for K4's atomics. grid = B, block = 1024.
// ---------------------------------------------------------------------------
__global__ void k_softmax(const float* __restrict__ mask, float* __restrict__ out) {
    int b   = blockIdx.x;
    int tid = threadIdx.x;
    const float4* sc = reinterpret_cast<const float4*>(out + BB * HH + 2 * BB * SS + b * SS);
    float4* attn1 = reinterpret_cast<float4*>(out + BB * HH + b * SS);
    float4* attn2 = reinterpret_cast<float4*>(out + BB * HH + BB * SS + b * SS);
    const float4* m4p = reinterpret_cast<const float4*>(mask + b * SS);

    __shared__ float red[32];
    int warp = tid >> 5, lane = tid & 31;

    float4 x = sc[tid];

    float mx = fmaxf(fmaxf(x.x, x.y), fmaxf(x.z, x.w));
    mx = warp_max(mx);
    if (lane == 0) red[warp] = mx;
    __syncthreads();
    if (tid < 32) {
        float t = red[tid];
        t = warp_max(t);
        if (tid == 0) red[0] = t;
    }
    __syncthreads();
    mx = red[0];
    __syncthreads();

    float4 p;
    p.x = __expf(x.x - mx); p.y = __expf(x.y - mx);
    p.z = __expf(x.z - mx); p.w = __expf(x.w - mx);

    float sm = p.x + p.y + p.z + p.w;
    sm = warp_sum(sm);
    if (lane == 0) red[warp] = sm;
    __syncthreads();
    if (tid < 32) {
        float t = red[tid];
        t = warp_sum(t);
        if (tid == 0) red[0] = t;
    }
    __syncthreads();
    float denom = red[0];
    __syncthreads();

    float4 m = m4p[tid];
    float4 a0;
    float inv = 1.f / denom;
    a0.x = p.x * inv * m.x; a0.y = p.y * inv * m.y;
    a0.z = p.z * inv * m.z; a0.w = p.w * inv * m.w;

    float s2 = a0.x + a0.y + a0.z + a0.w;
    s2 = warp_sum(s2);
    if (lane == 0) red[warp] = s2;
    __syncthreads();
    if (tid < 32) {
        float t = red[tid];
        t = warp_sum(t);
        if (tid == 0) red[0] = t;
    }
    __syncthreads();
    float inv2 = 1.f / (red[0] + 1e-20f);

    float4 a;
    a.x = a0.x * inv2; a.y = a0.y * inv2; a.z = a0.z * inv2; a.w = a0.w * inv2;
    attn1[tid] = a;
    attn2[tid] = a;

    out[b * HH + tid] = 0.f;
}

// ---------------------------------------------------------------------------
// K4: c_t[b][h] += sum_{s in chunk} attn[b,s] * eo[b,s,h]
// chunk = 32 -> grid (128, 16) = 2048 blocks; attn read as float4; 4
// independent accumulators per group of 4 s-rows for MLP. REDG merge.
// ---------------------------------------------------------------------------
#define K4_CHUNK 32
__global__ void k_context(const float* __restrict__ eo, float* __restrict__ out) {
    int b  = blockIdx.y;
    int s0 = blockIdx.x * K4_CHUNK;
    int t  = threadIdx.x;
    const float4* attn4 = reinterpret_cast<const float4*>(out + BB * HH + b * SS + s0);
    const float4* eob = reinterpret_cast<const float4*>(eo + ((size_t)(b * SS + s0)) * HH);

    float4 acc0 = make_float4(0.f, 0.f, 0.f, 0.f);
    float4 acc1 = make_float4(0.f, 0.f, 0.f, 0.f);
    float4 acc2 = make_float4(0.f, 0.f, 0.f, 0.f);
    float4 acc3 = make_float4(0.f, 0.f, 0.f, 0.f);

#pragma unroll
    for (int g = 0; g < K4_CHUNK / 4; g++) {
        float4 a4 = __ldg(attn4 + g);
        float4 e0 = __ldg(eob + (size_t)(g * 4 + 0) * (HH / 4) + t);
        float4 e1 = __ldg(eob + (size_t)(g * 4 + 1) * (HH / 4) + t);
        float4 e2 = __ldg(eob + (size_t)(g * 4 + 2) * (HH / 4) + t);
        float4 e3 = __ldg(eob + (size_t)(g * 4 + 3) * (HH / 4) + t);
        acc0.x += a4.x * e0.x; acc0.y += a4.x * e0.y; acc0.z += a4.x * e0.z; acc0.w += a4.x * e0.w;
        acc1.x += a4.y * e1.x; acc1.y += a4.y * e1.y; acc1.z += a4.y * e1.z; acc1.w += a4.y * e1.w;
        acc2.x += a4.z * e2.x; acc2.y += a4.z * e2.y; acc2.z += a4.z * e2.z; acc2.w += a4.z * e2.w;
        acc3.x += a4.w * e3.x; acc3.y += a4.w * e3.y; acc3.z += a4.w * e3.z; acc3.w += a4.w * e3.w;
    }
    float4 acc;
    acc.x = (acc0.x + acc1.x) + (acc2.x + acc3.x);
    acc.y = (acc0.y + acc1.y) + (acc2.y + acc3.y);
    acc.z = (acc0.z + acc1.z) + (acc2.z + acc3.z);
    acc.w = (acc0.w + acc1.w) + (acc2.w + acc3.w);

    float* ct = out + b * HH + t * 4;
    atomicAdd(ct + 0, acc.x);
    atomicAdd(ct + 1, acc.y);
    atomicAdd(ct + 2, acc.z);
    atomicAdd(ct + 3, acc.w);
}

// ---------------------------------------------------------------------------
extern "C" void kernel_launch(void* const* d_in, const int* in_sizes, int n_in,
                              void* d_out, int out_size) {
    const float* s_t_hat = (const float*)d_in[0];
    const float* enc_out = (const float*)d_in[1];
    const float* enc_fea = (const float*)d_in[2];
    const float* mask    = (const float*)d_in[3];
    const float* cov     = (const float*)d_in[4];
    const float* W_dec   = (const float*)d_in[5];
    const float* b_dec   = (const float*)d_in[6];
    const float* W_c     = (const float*)d_in[7];
    const float* v       = (const float*)d_in[8];
    float* out = (float*)d_out;

    float* scores = out + BB * HH + 2 * BB * SS;

    k_decproj<<<HH / 8, 256>>>(s_t_hat, W_dec, b_dec);
    k_scores<<<BB * SS / 32, 256>>>(enc_fea, cov, W_c, v, scores);
    k_softmax<<<BB, 1024>>>(mask, out);
    k_context<<<dim3(SS / K4_CHUNK, BB), 256>>>(enc_out, out);
}

// round 3
// speedup vs baseline: 1.0621x; 1.0621x over previous
#include <cuda_runtime.h>

#define BB 16
#define SS 4096
#define HH 1024

// scratch: dec_fea [B,H]
__device__ float g_dec[BB * HH];

__device__ __forceinline__ float tanh_fast(float x) {
    float y;
    asm("tanh.approx.f32 %0, %1;" : "=f"(y) : "f"(x));
    return y;
}

__device__ __forceinline__ float warp_sum(float v) {
#pragma unroll
    for (int o = 16; o > 0; o >>= 1) v += __shfl_xor_sync(0xffffffffu, v, o);
    return v;
}

__device__ __forceinline__ float warp_max(float v) {
#pragma unroll
    for (int o = 16; o > 0; o >>= 1) v = fmaxf(v, __shfl_xor_sync(0xffffffffu, v, o));
    return v;
}

// ---------------------------------------------------------------------------
// K1: dec[b][h] = sum_k s_t_hat[b][k] * W_dec[h][k] + b_dec[h]
// ---------------------------------------------------------------------------
__global__ void k_decproj(const float* __restrict__ s_t,
                          const float* __restrict__ W,
                          const float* __restrict__ bias) {
    int warp = threadIdx.x >> 5, lane = threadIdx.x & 31;
    int h = blockIdx.x * 8 + warp;

    float acc[BB];
#pragma unroll
    for (int b = 0; b < BB; b++) acc[b] = 0.f;

    const float4* Wrow = reinterpret_cast<const float4*>(W + (size_t)h * HH);
#pragma unroll
    for (int it = 0; it < 8; it++) {
        int k4 = it * 32 + lane;
        float4 w = __ldg(Wrow + k4);
#pragma unroll
        for (int b = 0; b < BB; b++) {
            float4 s4 = __ldg(reinterpret_cast<const float4*>(s_t + b * HH) + k4);
            acc[b] += w.x * s4.x + w.y * s4.y + w.z * s4.z + w.w * s4.w;
        }
    }
#pragma unroll
    for (int b = 0; b < BB; b++) {
        float r = warp_sum(acc[b]);
        if (lane == 0) g_dec[b * HH + h] = r + bias[h];
    }
}

// ---------------------------------------------------------------------------
// K2: scores[b][s] = sum_h tanh(ef[b,s,h] + dec[b,h] + cov[b,s]*Wc[h]) * v[h]
// 4 rows/warp; smem operands loaded once per iter, reused across rows.
// ---------------------------------------------------------------------------
#define ROWS_PER_WARP 4
__global__ void k_scores(const float* __restrict__ ef,
                         const float* __restrict__ cov,
                         const float* __restrict__ Wc,
                         const float* __restrict__ v,
                         float* __restrict__ scores) {
    __shared__ float dec_sm[HH], wc_sm[HH], v_sm[HH];
    const int rows_per_block = 8 * ROWS_PER_WARP;  // 32
    int b  = blockIdx.x / (SS / rows_per_block);
    int s0 = (blockIdx.x % (SS / rows_per_block)) * rows_per_block;

    for (int i = threadIdx.x; i < HH / 4; i += blockDim.x) {
        reinterpret_cast<float4*>(dec_sm)[i] = reinterpret_cast<const float4*>(g_dec + b * HH)[i];
        reinterpret_cast<float4*>(wc_sm)[i]  = reinterpret_cast<const float4*>(Wc)[i];
        reinterpret_cast<float4*>(v_sm)[i]   = reinterpret_cast<const float4*>(v)[i];
    }
    __syncthreads();

    int warp = threadIdx.x >> 5, lane = threadIdx.x & 31;
    int s = s0 + warp * ROWS_PER_WARP;

    float c[ROWS_PER_WARP];
    const float4* efr[ROWS_PER_WARP];
#pragma unroll
    for (int r = 0; r < ROWS_PER_WARP; r++) {
        c[r] = __ldg(cov + b * SS + s + r);
        efr[r] = reinterpret_cast<const float4*>(ef + ((size_t)(b * SS + s + r)) * HH);
    }

    float acc[ROWS_PER_WARP];
#pragma unroll
    for (int r = 0; r < ROWS_PER_WARP; r++) acc[r] = 0.f;

#pragma unroll
    for (int it = 0; it < 8; it++) {
        int k4 = it * 32 + lane;
        float4 d  = reinterpret_cast<const float4*>(dec_sm)[k4];
        float4 w  = reinterpret_cast<const float4*>(wc_sm)[k4];
        float4 vv = reinterpret_cast<const float4*>(v_sm)[k4];
        float4 f[ROWS_PER_WARP];
#pragma unroll
        for (int r = 0; r < ROWS_PER_WARP; r++) f[r] = __ldg(efr[r] + k4);
#pragma unroll
        for (int r = 0; r < ROWS_PER_WARP; r++) {
            acc[r] += tanh_fast(f[r].x + d.x + c[r] * w.x) * vv.x;
            acc[r] += tanh_fast(f[r].y + d.y + c[r] * w.y) * vv.y;
            acc[r] += tanh_fast(f[r].z + d.z + c[r] * w.z) * vv.z;
            acc[r] += tanh_fast(f[r].w + d.w + c[r] * w.w) * vv.w;
        }
    }
#pragma unroll
    for (int r = 0; r < ROWS_PER_WARP; r++) {
        float t = warp_sum(acc[r]);
        if (lane == 0) scores[b * SS + s + r] = t;
    }
}

// ---------------------------------------------------------------------------
// K3: masked softmax + renorm; writes attn twice; zeroes c_t.
// ---------------------------------------------------------------------------
__global__ void k_softmax(const float* __restrict__ mask, float* __restrict__ out) {
    int b   = blockIdx.x;
    int tid = threadIdx.x;
    const float4* sc = reinterpret_cast<const float4*>(out + BB * HH + 2 * BB * SS + b * SS);
    float4* attn1 = reinterpret_cast<float4*>(out + BB * HH + b * SS);
    float4* attn2 = reinterpret_cast<float4*>(out + BB * HH + BB * SS + b * SS);
    const float4* m4p = reinterpret_cast<const float4*>(mask + b * SS);

    __shared__ float red[32];
    int warp = tid >> 5, lane = tid & 31;

    float4 x = sc[tid];

    float mx = fmaxf(fmaxf(x.x, x.y), fmaxf(x.z, x.w));
    mx = warp_max(mx);
    if (lane == 0) red[warp] = mx;
    __syncthreads();
    if (tid < 32) {
        float t = red[tid];
        t = warp_max(t);
        if (tid == 0) red[0] = t;
    }
    __syncthreads();
    mx = red[0];
    __syncthreads();

    float4 p;
    p.x = __expf(x.x - mx); p.y = __expf(x.y - mx);
    p.z = __expf(x.z - mx); p.w = __expf(x.w - mx);

    float sm = p.x + p.y + p.z + p.w;
    sm = warp_sum(sm);
    if (lane == 0) red[warp] = sm;
    __syncthreads();
    if (tid < 32) {
        float t = red[tid];
        t = warp_sum(t);
        if (tid == 0) red[0] = t;
    }
    __syncthreads();
    float denom = red[0];
    __syncthreads();

    float4 m = m4p[tid];
    float4 a0;
    float inv = 1.f / denom;
    a0.x = p.x * inv * m.x; a0.y = p.y * inv * m.y;
    a0.z = p.z * inv * m.z; a0.w = p.w * inv * m.w;

    float s2 = a0.x + a0.y + a0.z + a0.w;
    s2 = warp_sum(s2);
    if (lane == 0) red[warp] = s2;
    __syncthreads();
    if (tid < 32) {
        float t = red[tid];
        t = warp_sum(t);
        if (tid == 0) red[0] = t;
    }
    __syncthreads();
    float inv2 = 1.f / (red[0] + 1e-20f);

    float4 a;
    a.x = a0.x * inv2; a.y = a0.y * inv2; a.z = a0.z * inv2; a.w = a0.w * inv2;
    attn1[tid] = a;
    attn2[tid] = a;

    out[b * HH + tid] = 0.f;
}

// ---------------------------------------------------------------------------
// K4: c_t[b][h] += sum_{s in chunk} attn[b,s] * eo[b,s,h]
// block = 128 threads covering HALF the h range (z selects which half);
// chunk = 64 s-rows. grid = (S/64, B, 2) = 2048 blocks of 4 warps.
// Low-reg simple loop (single float4 acc) keeps full occupancy; finer block
// granularity (13.8 blocks/SM) smooths the single-wave tail vs R1's 6.9.
// ---------------------------------------------------------------------------
#define K4_CHUNK 64
__global__ void __launch_bounds__(128) k_context(const float* __restrict__ eo,
                                                 float* __restrict__ out) {
    int b  = blockIdx.y;
    int s0 = blockIdx.x * K4_CHUNK;
    int t  = blockIdx.z * 128 + threadIdx.x;   // float4 index within h row
    const float* attn = out + BB * HH + b * SS;
    const float4* eob = reinterpret_cast<const float4*>(eo + ((size_t)b * SS) * HH);

    float4 acc = make_float4(0.f, 0.f, 0.f, 0.f);
#pragma unroll 4
    for (int i = 0; i < K4_CHUNK; i++) {
        int s = s0 + i;
        float a  = __ldg(attn + s);
        float4 e = __ldg(eob + (size_t)s * (HH / 4) + t);
        acc.x += a * e.x; acc.y += a * e.y;
        acc.z += a * e.z; acc.w += a * e.w;
    }
    float* ct = out + b * HH + t * 4;
    atomicAdd(ct + 0, acc.x);
    atomicAdd(ct + 1, acc.y);
    atomicAdd(ct + 2, acc.z);
    atomicAdd(ct + 3, acc.w);
}

// ---------------------------------------------------------------------------
extern "C" void kernel_launch(void* const* d_in, const int* in_sizes, int n_in,
                              void* d_out, int out_size) {
    const float* s_t_hat = (const float*)d_in[0];
    const float* enc_out = (const float*)d_in[1];
    const float* enc_fea = (const float*)d_in[2];
    const float* mask    = (const float*)d_in[3];
    const float* cov     = (const float*)d_in[4];
    const float* W_dec   = (const float*)d_in[5];
    const float* b_dec   = (const float*)d_in[6];
    const float* W_c     = (const float*)d_in[7];
    const float* v       = (const float*)d_in[8];
    float* out = (float*)d_out;

    float* scores = out + BB * HH + 2 * BB * SS;

    k_decproj<<<HH / 8, 256>>>(s_t_hat, W_dec, b_dec);
    k_scores<<<BB * SS / 32, 256>>>(enc_fea, cov, W_c, v, scores);
    k_softmax<<<BB, 1024>>>(mask, out);
    k_context<<<dim3(SS / K4_CHUNK, BB, 2), 128>>>(enc_out, out);
}